// round 1
// baseline (speedup 1.0000x reference)
#include <cuda_runtime.h>
#include <cstdint>

#define NSOL 40000
#define NHYD 60000
#define ESOL 640000
#define EHYD 960000
#define NGR  1000
#define EMB  128
#define NAT  133
#define NL   3
#define BN_EPS 1e-5f

// ---------------- scratch (device globals; no dynamic alloc) ----------------
__device__ float g_hs[NSOL * EMB];
__device__ float g_ms[NSOL * EMB];
__device__ float g_ts[NSOL * EMB];
__device__ float g_hh[NHYD * EMB];
__device__ float g_mh[NHYD * EMB];
__device__ float g_th[NHYD * EMB];
__device__ float g_pool_s[NGR * EMB];
__device__ float g_pool_h[NGR * EMB];
__device__ float g_cnt_s[NGR];
__device__ float g_cnt_h[NGR];
__device__ float g_stat[2 * EMB];

// ---------------- input projection: H = X @ W + b  (K = 133) ----------------
__global__ __launch_bounds__(256) void proj_kernel(
    const float* __restrict__ X, const float* __restrict__ W,
    const float* __restrict__ B, float* __restrict__ H, int N)
{
    __shared__ float Xs[64 * NAT];          // 34 KB
    int row0 = blockIdx.x * 64;
    int tid = threadIdx.x;
    int base = row0 * NAT;
    int limit = N * NAT - base;
    for (int i = tid; i < 64 * NAT; i += 256)
        Xs[i] = (i < limit) ? X[base + i] : 0.f;
    __syncthreads();

    int rg = tid >> 5;      // 0..7 (8 rows each)
    int cg = tid & 31;      // 0..31 (4 cols each)
    float acc[8][4];
#pragma unroll
    for (int i = 0; i < 8; i++) { acc[i][0]=acc[i][1]=acc[i][2]=acc[i][3]=0.f; }

    const float4* W4 = (const float4*)W;
    for (int k = 0; k < NAT; k++) {
        float4 bv = W4[k * 32 + cg];
#pragma unroll
        for (int i = 0; i < 8; i++) {
            float a = Xs[(rg * 8 + i) * NAT + k];
            acc[i][0] += a * bv.x; acc[i][1] += a * bv.y;
            acc[i][2] += a * bv.z; acc[i][3] += a * bv.w;
        }
    }
    float4 bb = ((const float4*)B)[cg];
#pragma unroll
    for (int i = 0; i < 8; i++) {
        int r = row0 + rg * 8 + i;
        if (r < N) {
            float4 o;
            o.x = acc[i][0] + bb.x; o.y = acc[i][1] + bb.y;
            o.z = acc[i][2] + bb.z; o.w = acc[i][3] + bb.w;
            ((float4*)H)[r * 32 + cg] = o;
        }
    }
}

// ---------------- edge scatter: M[dst] += H[src]  (vector L2 reduction) -----
__global__ __launch_bounds__(256) void edge_scatter(
    const float* __restrict__ H, float* __restrict__ M,
    const int* __restrict__ EI, int E)
{
    int gid = blockIdx.x * blockDim.x + threadIdx.x;
    int e = gid >> 5;
    if (e >= E) return;
    int lane = gid & 31;
    int src = EI[e];
    int dst = EI[E + e];
    float4 v = ((const float4*)H)[src * 32 + lane];
    float* p = M + (size_t)dst * EMB + lane * 4;
    asm volatile("red.global.add.v4.f32 [%0], {%1,%2,%3,%4};"
                 :: "l"(p), "f"(v.x), "f"(v.y), "f"(v.z), "f"(v.w) : "memory");
}

// ------- fused layer: Out = relu(M@W1+b1)@W2 + b2 + Res ; accumulate BN stats
__global__ __launch_bounds__(256, 2) void fused_layer(
    const float* __restrict__ M, const float* __restrict__ Res,
    const float* __restrict__ W1, const float* __restrict__ B1,
    const float* __restrict__ W2, const float* __restrict__ B2,
    float* __restrict__ Out, float* __restrict__ stat, int N)
{
    extern __shared__ float sm[];
    float* Ms = sm;                 // 64*128 floats = 32 KB
    float* Ts = sm + 64 * EMB;      // 64*256 floats = 64 KB
    int row0 = blockIdx.x * 64;
    int tid = threadIdx.x;

    {   // load M tile (float4, zero-pad past N)
        float4* Ms4 = (float4*)Ms;
        const float4* M4 = (const float4*)M;
        int limit4 = N * 32 - row0 * 32;
        for (int i = tid; i < 64 * 32; i += 256)
            Ms4[i] = (i < limit4) ? M4[row0 * 32 + i] : make_float4(0.f, 0.f, 0.f, 0.f);
    }
    __syncthreads();

    int rg = tid >> 5;   // row group (8 rows)
    int cg = tid & 31;   // col group

    // ---- stage A: T[64,256] = relu(M@W1 + b1), thread tile 8x8 ----
    float acc[8][8];
#pragma unroll
    for (int i = 0; i < 8; i++)
#pragma unroll
        for (int j = 0; j < 8; j++) acc[i][j] = 0.f;

    const float4* W1_4 = (const float4*)W1;
    const float4* Ms4r = (const float4*)Ms;
    for (int k4 = 0; k4 < 32; k4++) {
        float4 a4[8];
#pragma unroll
        for (int i = 0; i < 8; i++) a4[i] = Ms4r[(rg * 8 + i) * 32 + k4];  // broadcast LDS
#pragma unroll
        for (int kk = 0; kk < 4; kk++) {
            int k = k4 * 4 + kk;
            float4 b0 = W1_4[k * 64 + cg * 2];
            float4 b1 = W1_4[k * 64 + cg * 2 + 1];
#pragma unroll
            for (int i = 0; i < 8; i++) {
                float a = (kk == 0) ? a4[i].x : (kk == 1) ? a4[i].y : (kk == 2) ? a4[i].z : a4[i].w;
                acc[i][0] += a * b0.x; acc[i][1] += a * b0.y;
                acc[i][2] += a * b0.z; acc[i][3] += a * b0.w;
                acc[i][4] += a * b1.x; acc[i][5] += a * b1.y;
                acc[i][6] += a * b1.z; acc[i][7] += a * b1.w;
            }
        }
    }
    {   // write T with bias + relu
        float4 bA0 = ((const float4*)B1)[cg * 2];
        float4 bA1 = ((const float4*)B1)[cg * 2 + 1];
#pragma unroll
        for (int i = 0; i < 8; i++) {
            float* tp = Ts + (rg * 8 + i) * 256 + cg * 8;
            float4 o0, o1;
            o0.x = fmaxf(acc[i][0] + bA0.x, 0.f); o0.y = fmaxf(acc[i][1] + bA0.y, 0.f);
            o0.z = fmaxf(acc[i][2] + bA0.z, 0.f); o0.w = fmaxf(acc[i][3] + bA0.w, 0.f);
            o1.x = fmaxf(acc[i][4] + bA1.x, 0.f); o1.y = fmaxf(acc[i][5] + bA1.y, 0.f);
            o1.z = fmaxf(acc[i][6] + bA1.z, 0.f); o1.w = fmaxf(acc[i][7] + bA1.w, 0.f);
            ((float4*)tp)[0] = o0;
            ((float4*)tp)[1] = o1;
        }
    }
    __syncthreads();           // all Ms reads done, Ts complete
    float* sred = Ms;          // reuse: [0..127] sum, [128..255] sumsq
    sred[tid] = 0.f;
    __syncthreads();

    // ---- stage B: Out[64,128] = T@W2 + b2 + Res, thread tile 8x4 ----
    float acc2[8][4];
#pragma unroll
    for (int i = 0; i < 8; i++) { acc2[i][0]=acc2[i][1]=acc2[i][2]=acc2[i][3]=0.f; }

    const float4* W2_4 = (const float4*)W2;
    const float4* Ts4 = (const float4*)Ts;
    for (int k4 = 0; k4 < 64; k4++) {
        float4 a4[8];
#pragma unroll
        for (int i = 0; i < 8; i++) a4[i] = Ts4[(rg * 8 + i) * 64 + k4];
#pragma unroll
        for (int kk = 0; kk < 4; kk++) {
            int k = k4 * 4 + kk;
            float4 b = W2_4[k * 32 + cg];
#pragma unroll
            for (int i = 0; i < 8; i++) {
                float a = (kk == 0) ? a4[i].x : (kk == 1) ? a4[i].y : (kk == 2) ? a4[i].z : a4[i].w;
                acc2[i][0] += a * b.x; acc2[i][1] += a * b.y;
                acc2[i][2] += a * b.z; acc2[i][3] += a * b.w;
            }
        }
    }

    // ---- epilogue: bias + residual, write, BN stat reduction ----
    float4 bB = ((const float4*)B2)[cg];
    float ls0=0,ls1=0,ls2=0,ls3=0, lq0=0,lq1=0,lq2=0,lq3=0;
#pragma unroll
    for (int i = 0; i < 8; i++) {
        int r = row0 + rg * 8 + i;
        if (r < N) {
            float4 rv = ((const float4*)Res)[r * 32 + cg];
            float4 o;
            o.x = acc2[i][0] + bB.x + rv.x;
            o.y = acc2[i][1] + bB.y + rv.y;
            o.z = acc2[i][2] + bB.z + rv.z;
            o.w = acc2[i][3] + bB.w + rv.w;
            ((float4*)Out)[r * 32 + cg] = o;
            ls0 += o.x; ls1 += o.y; ls2 += o.z; ls3 += o.w;
            lq0 += o.x*o.x; lq1 += o.y*o.y; lq2 += o.z*o.z; lq3 += o.w*o.w;
        }
    }
    int c0 = cg * 4;
    atomicAdd(&sred[c0 + 0], ls0); atomicAdd(&sred[c0 + 1], ls1);
    atomicAdd(&sred[c0 + 2], ls2); atomicAdd(&sred[c0 + 3], ls3);
    atomicAdd(&sred[EMB + c0 + 0], lq0); atomicAdd(&sred[EMB + c0 + 1], lq1);
    atomicAdd(&sred[EMB + c0 + 2], lq2); atomicAdd(&sred[EMB + c0 + 3], lq3);
    __syncthreads();
    atomicAdd(&stat[tid], sred[tid]);   // tid 0..255 covers sum+sumsq
}

// ---------------- batchnorm apply (+optional relu) ----------------
__global__ __launch_bounds__(256) void bn_apply(
    const float* __restrict__ In, float* __restrict__ Out,
    const float* __restrict__ stat, const float* __restrict__ G,
    const float* __restrict__ Be, int N, int doRelu)
{
    __shared__ float sc[EMB], sh[EMB];
    if (threadIdx.x < EMB) {
        int c = threadIdx.x;
        float invN = 1.f / (float)N;
        float mu = stat[c] * invN;
        float var = stat[EMB + c] * invN - mu * mu;
        float s = rsqrtf(var + BN_EPS) * G[c];
        sc[c] = s;
        sh[c] = Be[c] - mu * s;
    }
    __syncthreads();
    int total4 = N * 32;
    for (int i = blockIdx.x * blockDim.x + threadIdx.x; i < total4; i += gridDim.x * blockDim.x) {
        int c4 = (i & 31) * 4;
        float4 v = ((const float4*)In)[i];
        v.x = v.x * sc[c4 + 0] + sh[c4 + 0];
        v.y = v.y * sc[c4 + 1] + sh[c4 + 1];
        v.z = v.z * sc[c4 + 2] + sh[c4 + 2];
        v.w = v.w * sc[c4 + 3] + sh[c4 + 3];
        if (doRelu) {
            v.x = fmaxf(v.x, 0.f); v.y = fmaxf(v.y, 0.f);
            v.z = fmaxf(v.z, 0.f); v.w = fmaxf(v.w, 0.f);
        }
        ((float4*)Out)[i] = v;
    }
}

// ---------------- mean pool (weighted for hydrated) ----------------
__global__ __launch_bounds__(256) void pool_kernel(
    const float* __restrict__ H, const int* __restrict__ batch,
    const int* __restrict__ mask, float* __restrict__ P,
    float* __restrict__ C, int N)
{
    int gid = blockIdx.x * blockDim.x + threadIdx.x;
    int r = gid >> 5;
    if (r >= N) return;
    int lane = gid & 31;
    if (mask && mask[r] == 0) return;
    int g = batch[r];
    float4 v = ((const float4*)H)[r * 32 + lane];
    float* p = P + (size_t)g * EMB + lane * 4;
    asm volatile("red.global.add.v4.f32 [%0], {%1,%2,%3,%4};"
                 :: "l"(p), "f"(v.x), "f"(v.y), "f"(v.z), "f"(v.w) : "memory");
    if (lane == 0) atomicAdd(&C[g], 1.f);
}

// ---------------- head MLP: [NG,256] -> 128 -> 64 -> 1 ----------------
__global__ __launch_bounds__(128) void head_kernel(
    const float* __restrict__ Ps, const float* __restrict__ Cs,
    const float* __restrict__ Ph, const float* __restrict__ Ch,
    const float* __restrict__ fw1, const float* __restrict__ fb1,
    const float* __restrict__ fw2, const float* __restrict__ fb2,
    const float* __restrict__ fw3, const float* __restrict__ fb3,
    float* __restrict__ out)
{
    __shared__ float rep[256], o1[128], o2[64];
    int g = blockIdx.x;
    int tid = threadIdx.x;
    float cs = fmaxf(Cs[g], 1.f), ch = fmaxf(Ch[g], 1.f);
    rep[tid] = Ps[g * EMB + tid] / cs;
    rep[128 + tid] = Ph[g * EMB + tid] / ch;
    __syncthreads();
    float s = fb1[tid];
    for (int k = 0; k < 256; k++) s += rep[k] * fw1[k * 128 + tid];
    o1[tid] = fmaxf(s, 0.f);
    __syncthreads();
    if (tid < 64) {
        float s2 = fb2[tid];
        for (int k = 0; k < 128; k++) s2 += o1[k] * fw2[k * 64 + tid];
        o2[tid] = fmaxf(s2, 0.f);
    }
    __syncthreads();
    if (tid == 0) {
        float s3 = fb3[0];
        for (int k = 0; k < 64; k++) s3 += o2[k] * fw3[k];
        out[g] = s3;
    }
}

// ---------------- launcher ----------------
extern "C" void kernel_launch(void* const* d_in, const int* in_sizes, int n_in,
                              void* d_out, int out_size)
{
    const float* solute_x = (const float*)d_in[0];
    const float* hyd_x    = (const float*)d_in[1];
    const float* Wx_s = (const float*)d_in[2];
    const float* bx_s = (const float*)d_in[3];
    const float* Wx_h = (const float*)d_in[4];
    const float* bx_h = (const float*)d_in[5];
    const float* w1_s = (const float*)d_in[6];
    const float* b1_s = (const float*)d_in[7];
    const float* w2_s = (const float*)d_in[8];
    const float* b2_s = (const float*)d_in[9];
    const float* gg_s = (const float*)d_in[10];
    const float* be_s = (const float*)d_in[11];
    const float* w1_h = (const float*)d_in[12];
    const float* b1_h = (const float*)d_in[13];
    const float* w2_h = (const float*)d_in[14];
    const float* b2_h = (const float*)d_in[15];
    const float* gg_h = (const float*)d_in[16];
    const float* be_h = (const float*)d_in[17];
    const float* fcw1 = (const float*)d_in[18];
    const float* fcb1 = (const float*)d_in[19];
    const float* fcw2 = (const float*)d_in[20];
    const float* fcb2 = (const float*)d_in[21];
    const float* fcw3 = (const float*)d_in[22];
    const float* fcb3 = (const float*)d_in[23];
    const int* ei_s   = (const int*)d_in[24];
    const int* ei_h   = (const int*)d_in[25];
    const int* batch_s = (const int*)d_in[26];
    const int* batch_h = (const int*)d_in[27];
    const int* mask_h  = (const int*)d_in[28];

    float *hs, *ms, *ts, *hh, *mh, *th, *ps, *ph, *cs, *ch, *stat;
    cudaGetSymbolAddress((void**)&hs, g_hs);
    cudaGetSymbolAddress((void**)&ms, g_ms);
    cudaGetSymbolAddress((void**)&ts, g_ts);
    cudaGetSymbolAddress((void**)&hh, g_hh);
    cudaGetSymbolAddress((void**)&mh, g_mh);
    cudaGetSymbolAddress((void**)&th, g_th);
    cudaGetSymbolAddress((void**)&ps, g_pool_s);
    cudaGetSymbolAddress((void**)&ph, g_pool_h);
    cudaGetSymbolAddress((void**)&cs, g_cnt_s);
    cudaGetSymbolAddress((void**)&ch, g_cnt_h);
    cudaGetSymbolAddress((void**)&stat, g_stat);

    cudaFuncSetAttribute(fused_layer, cudaFuncAttributeMaxDynamicSharedMemorySize, 98304);

    const size_t szs = (size_t)NSOL * EMB * sizeof(float);
    const size_t szh = (size_t)NHYD * EMB * sizeof(float);
    const int nbS = (NSOL + 63) / 64;
    const int nbH = (NHYD + 63) / 64;

    // input projections
    proj_kernel<<<nbS, 256>>>(solute_x, Wx_s, bx_s, hs, NSOL);
    proj_kernel<<<nbH, 256>>>(hyd_x, Wx_h, bx_h, hh, NHYD);

    for (int l = 0; l < NL; l++) {
        // ---- solute branch ----
        cudaMemcpyAsync(ms, hs, szs, cudaMemcpyDeviceToDevice);
        edge_scatter<<<ESOL / 8, 256>>>(hs, ms, ei_s, ESOL);
        cudaMemsetAsync(stat, 0, 2 * EMB * sizeof(float));
        fused_layer<<<nbS, 256, 98304>>>(ms, hs,
            w1_s + (size_t)l * EMB * 2 * EMB, b1_s + l * 2 * EMB,
            w2_s + (size_t)l * 2 * EMB * EMB, b2_s + l * EMB,
            ts, stat, NSOL);
        bn_apply<<<1024, 256>>>(ts, hs, stat, gg_s + l * EMB, be_s + l * EMB,
                                NSOL, (l < NL - 1) ? 1 : 0);
        // ---- hydrated branch ----
        cudaMemcpyAsync(mh, hh, szh, cudaMemcpyDeviceToDevice);
        edge_scatter<<<EHYD / 8, 256>>>(hh, mh, ei_h, EHYD);
        cudaMemsetAsync(stat, 0, 2 * EMB * sizeof(float));
        fused_layer<<<nbH, 256, 98304>>>(mh, hh,
            w1_h + (size_t)l * EMB * 2 * EMB, b1_h + l * 2 * EMB,
            w2_h + (size_t)l * 2 * EMB * EMB, b2_h + l * EMB,
            th, stat, NHYD);
        bn_apply<<<1024, 256>>>(th, hh, stat, gg_h + l * EMB, be_h + l * EMB,
                                NHYD, (l < NL - 1) ? 1 : 0);
    }

    // pooling
    cudaMemsetAsync(ps, 0, (size_t)NGR * EMB * sizeof(float));
    cudaMemsetAsync(ph, 0, (size_t)NGR * EMB * sizeof(float));
    cudaMemsetAsync(cs, 0, NGR * sizeof(float));
    cudaMemsetAsync(ch, 0, NGR * sizeof(float));
    pool_kernel<<<(NSOL * 32 + 255) / 256, 256>>>(hs, batch_s, nullptr, ps, cs, NSOL);
    pool_kernel<<<(NHYD * 32 + 255) / 256, 256>>>(hh, batch_h, mask_h, ph, ch, NHYD);

    // head MLP
    head_kernel<<<NGR, 128>>>(ps, cs, ph, ch, fcw1, fcb1, fcw2, fcb2, fcw3, fcb3,
                              (float*)d_out);
}

// round 2
// speedup vs baseline: 1.1711x; 1.1711x over previous
#include <cuda_runtime.h>
#include <cstdint>

#define NSOL 40000
#define NHYD 60000
#define ESOL 640000
#define EHYD 960000
#define NGR  1000
#define EMB  128
#define NAT  133
#define NL   3
#define BN_EPS 1e-5f

typedef unsigned long long ull;

// ---------------- packed fp32x2 helpers (sm_100+) ----------------
__device__ __forceinline__ ull ffma2(ull a, ull b, ull c) {
    ull d;
    asm("fma.rn.f32x2 %0, %1, %2, %3;" : "=l"(d) : "l"(a), "l"(b), "l"(c));
    return d;
}
__device__ __forceinline__ ull dup2(float a) {
    ull r; asm("mov.b64 %0, {%1, %1};" : "=l"(r) : "f"(a)); return r;
}
__device__ __forceinline__ float2 unpk(ull v) {
    float2 r; asm("mov.b64 {%0, %1}, %2;" : "=f"(r.x), "=f"(r.y) : "l"(v)); return r;
}

// ---------------- scratch (device globals; no dynamic alloc) ----------------
__device__ float g_hs[NSOL * EMB];
__device__ float g_ms[NSOL * EMB];
__device__ float g_ts[NSOL * EMB];
__device__ float g_hh[NHYD * EMB];
__device__ float g_mh[NHYD * EMB];
__device__ float g_th[NHYD * EMB];
__device__ float g_pool_s[NGR * EMB];
__device__ float g_pool_h[NGR * EMB];
__device__ float g_cnt_s[NGR];
__device__ float g_cnt_h[NGR];
__device__ float g_stat[2 * EMB];

// ---------------- input projection: H = X @ W + b  (K = 133), dual write ----
__global__ __launch_bounds__(256) void proj_kernel(
    const float* __restrict__ X, const float* __restrict__ W,
    const float* __restrict__ B, float* __restrict__ H,
    float* __restrict__ H2, int N)
{
    __shared__ float Xs[64 * NAT];          // 34 KB
    int row0 = blockIdx.x * 64;
    int tid = threadIdx.x;
    int base = row0 * NAT;
    int limit = N * NAT - base;
    for (int i = tid; i < 64 * NAT; i += 256)
        Xs[i] = (i < limit) ? X[base + i] : 0.f;
    __syncthreads();

    int rg = tid >> 5;      // 0..7 (8 rows each)
    int cg = tid & 31;      // 4 cols each (packed into 2 ulls)

    ull acc[8][2];
    {
        const ull* Bu = (const ull*)B;
        ull b0 = Bu[cg * 2], b1 = Bu[cg * 2 + 1];
#pragma unroll
        for (int i = 0; i < 8; i++) { acc[i][0] = b0; acc[i][1] = b1; }
    }
    const ulonglong2* Wu = (const ulonglong2*)W;   // 32 uint128 per 128-float row
#pragma unroll 4
    for (int k = 0; k < NAT; k++) {
        ulonglong2 bv = Wu[k * 32 + cg];           // cols 4cg..4cg+3
#pragma unroll
        for (int i = 0; i < 8; i++) {
            ull ad = dup2(Xs[(rg * 8 + i) * NAT + k]);
            acc[i][0] = ffma2(ad, bv.x, acc[i][0]);
            acc[i][1] = ffma2(ad, bv.y, acc[i][1]);
        }
    }
#pragma unroll
    for (int i = 0; i < 8; i++) {
        int r = row0 + rg * 8 + i;
        if (r < N) {
            float2 p0 = unpk(acc[i][0]), p1 = unpk(acc[i][1]);
            float4 o; o.x = p0.x; o.y = p0.y; o.z = p1.x; o.w = p1.y;
            ((float4*)H)[r * 32 + cg] = o;
            ((float4*)H2)[r * 32 + cg] = o;
        }
    }
}

// ---------------- edge scatter: M[dst] += H[src]  (vector L2 reduction) -----
__global__ __launch_bounds__(256) void edge_scatter(
    const float* __restrict__ H, float* __restrict__ M,
    const int* __restrict__ EI, int E)
{
    int gid = blockIdx.x * blockDim.x + threadIdx.x;
    int e = gid >> 5;
    if (e >= E) return;
    int lane = gid & 31;
    int src = EI[e];
    int dst = EI[E + e];
    float4 v = ((const float4*)H)[src * 32 + lane];
    float* p = M + (size_t)dst * EMB + lane * 4;
    asm volatile("red.global.add.v4.f32 [%0], {%1,%2,%3,%4};"
                 :: "l"(p), "f"(v.x), "f"(v.y), "f"(v.z), "f"(v.w) : "memory");
}

// ------- fused layer: Out = relu(M@W1+b1)@W2 + b2 + Res ; accumulate BN stats
// FMA2 column-pair packed GEMMs.
__global__ __launch_bounds__(256, 2) void fused_layer(
    const float* __restrict__ M, const float* __restrict__ Res,
    const float* __restrict__ W1, const float* __restrict__ B1,
    const float* __restrict__ W2, const float* __restrict__ B2,
    float* __restrict__ Out, float* __restrict__ stat, int N)
{
    extern __shared__ float sm[];
    float* Ms = sm;                 // 64*128 floats = 32 KB
    float* Ts = sm + 64 * EMB;      // 64*256 floats = 64 KB
    int row0 = blockIdx.x * 64;
    int tid = threadIdx.x;

    {   // load M tile (float4, zero-pad past N)
        float4* Ms4 = (float4*)Ms;
        const float4* M4 = (const float4*)M;
        int limit4 = N * 32 - row0 * 32;
        for (int i = tid; i < 64 * 32; i += 256)
            Ms4[i] = (i < limit4) ? M4[row0 * 32 + i] : make_float4(0.f, 0.f, 0.f, 0.f);
    }
    __syncthreads();

    int rg = tid >> 5;   // row group (8 rows)
    int cg = tid & 31;

    // ---- stage A: T[64,256] = relu(M@W1 + b1)
    // thread covers cols {4cg..4cg+3} and {128+4cg..128+4cg+3} (two contiguous
    // warp-wide 512B LDG groups), packed in 4 ull accumulators per row.
    ull accA[8][4];
    {
        const ull* B1u = (const ull*)B1;
        ull b0 = B1u[2 * cg], b1 = B1u[2 * cg + 1];
        ull b2 = B1u[64 + 2 * cg], b3 = B1u[64 + 2 * cg + 1];
#pragma unroll
        for (int i = 0; i < 8; i++) {
            accA[i][0] = b0; accA[i][1] = b1; accA[i][2] = b2; accA[i][3] = b3;
        }
    }
    const float4* Ms4r = (const float4*)Ms;
    const ulonglong2* W1u = (const ulonglong2*)W1;   // 64 uint128 per 256-float row
    for (int k4 = 0; k4 < 32; k4++) {
        float4 a4[8];
#pragma unroll
        for (int i = 0; i < 8; i++) a4[i] = Ms4r[(rg * 8 + i) * 32 + k4];  // broadcast
#pragma unroll
        for (int kk = 0; kk < 4; kk++) {
            int k = k4 * 4 + kk;
            ulonglong2 bv0 = W1u[k * 64 + cg];        // cols 4cg..4cg+3
            ulonglong2 bv1 = W1u[k * 64 + 32 + cg];   // cols 128+4cg..
#pragma unroll
            for (int i = 0; i < 8; i++) {
                float a = (kk == 0) ? a4[i].x : (kk == 1) ? a4[i].y : (kk == 2) ? a4[i].z : a4[i].w;
                ull ad = dup2(a);
                accA[i][0] = ffma2(ad, bv0.x, accA[i][0]);
                accA[i][1] = ffma2(ad, bv0.y, accA[i][1]);
                accA[i][2] = ffma2(ad, bv1.x, accA[i][2]);
                accA[i][3] = ffma2(ad, bv1.y, accA[i][3]);
            }
        }
    }
    {   // write T with relu (two float4 groups per row)
#pragma unroll
        for (int i = 0; i < 8; i++) {
            float2 p0 = unpk(accA[i][0]), p1 = unpk(accA[i][1]);
            float2 p2 = unpk(accA[i][2]), p3 = unpk(accA[i][3]);
            float4 o0, o1;
            o0.x = fmaxf(p0.x, 0.f); o0.y = fmaxf(p0.y, 0.f);
            o0.z = fmaxf(p1.x, 0.f); o0.w = fmaxf(p1.y, 0.f);
            o1.x = fmaxf(p2.x, 0.f); o1.y = fmaxf(p2.y, 0.f);
            o1.z = fmaxf(p3.x, 0.f); o1.w = fmaxf(p3.y, 0.f);
            float* tp = Ts + (rg * 8 + i) * 256;
            *(float4*)(tp + 4 * cg) = o0;
            *(float4*)(tp + 128 + 4 * cg) = o1;
        }
    }
    __syncthreads();           // Ts complete; Ms free
    float* sred = Ms;          // reuse: [0..127] sum, [128..255] sumsq
    sred[tid] = 0.f;
    __syncthreads();

    // ---- stage B: Out[64,128] = T@W2 + b2 + Res, cols 4cg..4cg+3 packed
    ull accB[8][2];
    {
        const ull* B2u = (const ull*)B2;
        ull b0 = B2u[2 * cg], b1 = B2u[2 * cg + 1];
#pragma unroll
        for (int i = 0; i < 8; i++) { accB[i][0] = b0; accB[i][1] = b1; }
    }
    const float4* Ts4 = (const float4*)Ts;
    const ulonglong2* W2u = (const ulonglong2*)W2;   // 32 uint128 per 128-float row
    for (int k4 = 0; k4 < 64; k4++) {
        float4 a4[8];
#pragma unroll
        for (int i = 0; i < 8; i++) a4[i] = Ts4[(rg * 8 + i) * 64 + k4];
#pragma unroll
        for (int kk = 0; kk < 4; kk++) {
            int k = k4 * 4 + kk;
            ulonglong2 bv = W2u[k * 32 + cg];
#pragma unroll
            for (int i = 0; i < 8; i++) {
                float a = (kk == 0) ? a4[i].x : (kk == 1) ? a4[i].y : (kk == 2) ? a4[i].z : a4[i].w;
                ull ad = dup2(a);
                accB[i][0] = ffma2(ad, bv.x, accB[i][0]);
                accB[i][1] = ffma2(ad, bv.y, accB[i][1]);
            }
        }
    }

    // ---- epilogue: bias(already) + residual, write, BN stat reduction ----
    float ls0=0,ls1=0,ls2=0,ls3=0, lq0=0,lq1=0,lq2=0,lq3=0;
#pragma unroll
    for (int i = 0; i < 8; i++) {
        int r = row0 + rg * 8 + i;
        if (r < N) {
            float2 p0 = unpk(accB[i][0]), p1 = unpk(accB[i][1]);
            float4 rv = ((const float4*)Res)[r * 32 + cg];
            float4 o;
            o.x = p0.x + rv.x;
            o.y = p0.y + rv.y;
            o.z = p1.x + rv.z;
            o.w = p1.y + rv.w;
            ((float4*)Out)[r * 32 + cg] = o;
            ls0 += o.x; ls1 += o.y; ls2 += o.z; ls3 += o.w;
            lq0 += o.x*o.x; lq1 += o.y*o.y; lq2 += o.z*o.z; lq3 += o.w*o.w;
        }
    }
    int c0 = cg * 4;
    atomicAdd(&sred[c0 + 0], ls0); atomicAdd(&sred[c0 + 1], ls1);
    atomicAdd(&sred[c0 + 2], ls2); atomicAdd(&sred[c0 + 3], ls3);
    atomicAdd(&sred[EMB + c0 + 0], lq0); atomicAdd(&sred[EMB + c0 + 1], lq1);
    atomicAdd(&sred[EMB + c0 + 2], lq2); atomicAdd(&sred[EMB + c0 + 3], lq3);
    __syncthreads();
    atomicAdd(&stat[tid], sred[tid]);   // tid 0..255 covers sum+sumsq
}

// ---------------- batchnorm apply (+optional relu), optional dual write -----
__global__ __launch_bounds__(256) void bn_apply(
    const float* __restrict__ In, float* __restrict__ Out,
    float* __restrict__ Out2,
    const float* __restrict__ stat, const float* __restrict__ G,
    const float* __restrict__ Be, int N, int doRelu)
{
    __shared__ float sc[EMB], sh[EMB];
    if (threadIdx.x < EMB) {
        int c = threadIdx.x;
        float invN = 1.f / (float)N;
        float mu = stat[c] * invN;
        float var = stat[EMB + c] * invN - mu * mu;
        float s = rsqrtf(var + BN_EPS) * G[c];
        sc[c] = s;
        sh[c] = Be[c] - mu * s;
    }
    __syncthreads();
    int total4 = N * 32;
    for (int i = blockIdx.x * blockDim.x + threadIdx.x; i < total4; i += gridDim.x * blockDim.x) {
        int c4 = (i & 31) * 4;
        float4 v = ((const float4*)In)[i];
        v.x = v.x * sc[c4 + 0] + sh[c4 + 0];
        v.y = v.y * sc[c4 + 1] + sh[c4 + 1];
        v.z = v.z * sc[c4 + 2] + sh[c4 + 2];
        v.w = v.w * sc[c4 + 3] + sh[c4 + 3];
        if (doRelu) {
            v.x = fmaxf(v.x, 0.f); v.y = fmaxf(v.y, 0.f);
            v.z = fmaxf(v.z, 0.f); v.w = fmaxf(v.w, 0.f);
        }
        ((float4*)Out)[i] = v;
        if (Out2) ((float4*)Out2)[i] = v;
    }
}

// ---------------- mean pool (weighted for hydrated) ----------------
__global__ __launch_bounds__(256) void pool_kernel(
    const float* __restrict__ H, const int* __restrict__ batch,
    const int* __restrict__ mask, float* __restrict__ P,
    float* __restrict__ C, int N)
{
    int gid = blockIdx.x * blockDim.x + threadIdx.x;
    int r = gid >> 5;
    if (r >= N) return;
    int lane = gid & 31;
    if (mask && mask[r] == 0) return;
    int g = batch[r];
    float4 v = ((const float4*)H)[r * 32 + lane];
    float* p = P + (size_t)g * EMB + lane * 4;
    asm volatile("red.global.add.v4.f32 [%0], {%1,%2,%3,%4};"
                 :: "l"(p), "f"(v.x), "f"(v.y), "f"(v.z), "f"(v.w) : "memory");
    if (lane == 0) atomicAdd(&C[g], 1.f);
}

// ---------------- head MLP: [NG,256] -> 128 -> 64 -> 1 ----------------
__global__ __launch_bounds__(128) void head_kernel(
    const float* __restrict__ Ps, const float* __restrict__ Cs,
    const float* __restrict__ Ph, const float* __restrict__ Ch,
    const float* __restrict__ fw1, const float* __restrict__ fb1,
    const float* __restrict__ fw2, const float* __restrict__ fb2,
    const float* __restrict__ fw3, const float* __restrict__ fb3,
    float* __restrict__ out)
{
    __shared__ float rep[256], o1[128], o2[64];
    int g = blockIdx.x;
    int tid = threadIdx.x;
    float cs = fmaxf(Cs[g], 1.f), ch = fmaxf(Ch[g], 1.f);
    rep[tid] = Ps[g * EMB + tid] / cs;
    rep[128 + tid] = Ph[g * EMB + tid] / ch;
    __syncthreads();
    float s = fb1[tid];
    for (int k = 0; k < 256; k++) s += rep[k] * fw1[k * 128 + tid];
    o1[tid] = fmaxf(s, 0.f);
    __syncthreads();
    if (tid < 64) {
        float s2 = fb2[tid];
        for (int k = 0; k < 128; k++) s2 += o1[k] * fw2[k * 64 + tid];
        o2[tid] = fmaxf(s2, 0.f);
    }
    __syncthreads();
    if (tid == 0) {
        float s3 = fb3[0];
        for (int k = 0; k < 64; k++) s3 += o2[k] * fw3[k];
        out[g] = s3;
    }
}

// ---------------- launcher ----------------
extern "C" void kernel_launch(void* const* d_in, const int* in_sizes, int n_in,
                              void* d_out, int out_size)
{
    const float* solute_x = (const float*)d_in[0];
    const float* hyd_x    = (const float*)d_in[1];
    const float* Wx_s = (const float*)d_in[2];
    const float* bx_s = (const float*)d_in[3];
    const float* Wx_h = (const float*)d_in[4];
    const float* bx_h = (const float*)d_in[5];
    const float* w1_s = (const float*)d_in[6];
    const float* b1_s = (const float*)d_in[7];
    const float* w2_s = (const float*)d_in[8];
    const float* b2_s = (const float*)d_in[9];
    const float* gg_s = (const float*)d_in[10];
    const float* be_s = (const float*)d_in[11];
    const float* w1_h = (const float*)d_in[12];
    const float* b1_h = (const float*)d_in[13];
    const float* w2_h = (const float*)d_in[14];
    const float* b2_h = (const float*)d_in[15];
    const float* gg_h = (const float*)d_in[16];
    const float* be_h = (const float*)d_in[17];
    const float* fcw1 = (const float*)d_in[18];
    const float* fcb1 = (const float*)d_in[19];
    const float* fcw2 = (const float*)d_in[20];
    const float* fcb2 = (const float*)d_in[21];
    const float* fcw3 = (const float*)d_in[22];
    const float* fcb3 = (const float*)d_in[23];
    const int* ei_s   = (const int*)d_in[24];
    const int* ei_h   = (const int*)d_in[25];
    const int* batch_s = (const int*)d_in[26];
    const int* batch_h = (const int*)d_in[27];
    const int* mask_h  = (const int*)d_in[28];

    float *hs, *ms, *ts, *hh, *mh, *th, *ps, *ph, *cs, *ch, *stat;
    cudaGetSymbolAddress((void**)&hs, g_hs);
    cudaGetSymbolAddress((void**)&ms, g_ms);
    cudaGetSymbolAddress((void**)&ts, g_ts);
    cudaGetSymbolAddress((void**)&hh, g_hh);
    cudaGetSymbolAddress((void**)&mh, g_mh);
    cudaGetSymbolAddress((void**)&th, g_th);
    cudaGetSymbolAddress((void**)&ps, g_pool_s);
    cudaGetSymbolAddress((void**)&ph, g_pool_h);
    cudaGetSymbolAddress((void**)&cs, g_cnt_s);
    cudaGetSymbolAddress((void**)&ch, g_cnt_h);
    cudaGetSymbolAddress((void**)&stat, g_stat);

    cudaFuncSetAttribute(fused_layer, cudaFuncAttributeMaxDynamicSharedMemorySize, 98304);

    const int nbS = (NSOL + 63) / 64;
    const int nbH = (NHYD + 63) / 64;

    // input projections (dual write: h and m for layer-0 scatter base)
    proj_kernel<<<nbS, 256>>>(solute_x, Wx_s, bx_s, hs, ms, NSOL);
    proj_kernel<<<nbH, 256>>>(hyd_x, Wx_h, bx_h, hh, mh, NHYD);

    for (int l = 0; l < NL; l++) {
        int notLast = (l < NL - 1) ? 1 : 0;
        // ---- solute branch ----
        edge_scatter<<<ESOL / 8, 256>>>(hs, ms, ei_s, ESOL);
        cudaMemsetAsync(stat, 0, 2 * EMB * sizeof(float));
        fused_layer<<<nbS, 256, 98304>>>(ms, hs,
            w1_s + (size_t)l * EMB * 2 * EMB, b1_s + l * 2 * EMB,
            w2_s + (size_t)l * 2 * EMB * EMB, b2_s + l * EMB,
            ts, stat, NSOL);
        bn_apply<<<1024, 256>>>(ts, hs, notLast ? ms : nullptr,
                                stat, gg_s + l * EMB, be_s + l * EMB,
                                NSOL, notLast);
        // ---- hydrated branch ----
        edge_scatter<<<EHYD / 8, 256>>>(hh, mh, ei_h, EHYD);
        cudaMemsetAsync(stat, 0, 2 * EMB * sizeof(float));
        fused_layer<<<nbH, 256, 98304>>>(mh, hh,
            w1_h + (size_t)l * EMB * 2 * EMB, b1_h + l * 2 * EMB,
            w2_h + (size_t)l * 2 * EMB * EMB, b2_h + l * EMB,
            th, stat, NHYD);
        bn_apply<<<1024, 256>>>(th, hh, notLast ? mh : nullptr,
                                stat, gg_h + l * EMB, be_h + l * EMB,
                                NHYD, notLast);
    }

    // pooling
    cudaMemsetAsync(ps, 0, (size_t)NGR * EMB * sizeof(float));
    cudaMemsetAsync(ph, 0, (size_t)NGR * EMB * sizeof(float));
    cudaMemsetAsync(cs, 0, NGR * sizeof(float));
    cudaMemsetAsync(ch, 0, NGR * sizeof(float));
    pool_kernel<<<(NSOL * 32 + 255) / 256, 256>>>(hs, batch_s, nullptr, ps, cs, NSOL);
    pool_kernel<<<(NHYD * 32 + 255) / 256, 256>>>(hh, batch_h, mask_h, ph, ch, NHYD);

    // head MLP
    head_kernel<<<NGR, 128>>>(ps, cs, ph, ch, fcw1, fcb1, fcw2, fcb2, fcw3, fcb3,
                              (float*)d_out);
}

// round 3
// speedup vs baseline: 1.7180x; 1.4669x over previous
#include <cuda_runtime.h>
#include <cstdint>

#define NSOL 40000
#define NHYD 60000
#define ESOL 640000
#define EHYD 960000
#define NGR  1000
#define EMB  128
#define NAT  133
#define NL   3
#define BN_EPS 1e-5f

typedef unsigned long long ull;

// ---------------- packed fp32x2 helpers (sm_100+) ----------------
__device__ __forceinline__ ull ffma2(ull a, ull b, ull c) {
    ull d;
    asm("fma.rn.f32x2 %0, %1, %2, %3;" : "=l"(d) : "l"(a), "l"(b), "l"(c));
    return d;
}
__device__ __forceinline__ ull dup2(float a) {
    ull r; asm("mov.b64 %0, {%1, %1};" : "=l"(r) : "f"(a)); return r;
}
__device__ __forceinline__ float2 unpk(ull v) {
    float2 r; asm("mov.b64 {%0, %1}, %2;" : "=f"(r.x), "=f"(r.y) : "l"(v)); return r;
}
__device__ __forceinline__ void cp16(uint32_t saddr, const void* g) {
    asm volatile("cp.async.cg.shared.global [%0], [%1], 16;" :: "r"(saddr), "l"(g));
}
#define CP_COMMIT() asm volatile("cp.async.commit_group;")
#define CP_WAIT1()  asm volatile("cp.async.wait_group 1;")
#define CP_WAIT0()  asm volatile("cp.async.wait_group 0;")

// ---------------- scratch (device globals; no dynamic alloc) ----------------
__device__ float g_hs[NSOL * EMB];
__device__ float g_ms[NSOL * EMB];
__device__ float g_ts[NSOL * EMB];
__device__ float g_hh[NHYD * EMB];
__device__ float g_mh[NHYD * EMB];
__device__ float g_th[NHYD * EMB];
__device__ float g_pool_s[NGR * EMB];
__device__ float g_pool_h[NGR * EMB];
__device__ float g_cnt_s[NGR];
__device__ float g_cnt_h[NGR];
__device__ float g_stat[2 * EMB];
// CSR scratch
__device__ int g_deg[NHYD];
__device__ int g_off_s[NSOL + 1];
__device__ int g_off_h[NHYD + 1];
__device__ int g_csr_s[ESOL];
__device__ int g_csr_h[EHYD];
__device__ int g_bsum[64];

// ---------------- input projection: H = X @ W + b  (K = 133) ----------------
__global__ __launch_bounds__(256) void proj_kernel(
    const float* __restrict__ X, const float* __restrict__ W,
    const float* __restrict__ B, float* __restrict__ H, int N)
{
    __shared__ float Xs[64 * NAT];          // 34 KB
    int row0 = blockIdx.x * 64;
    int tid = threadIdx.x;
    int base = row0 * NAT;
    int limit = N * NAT - base;
    for (int i = tid; i < 64 * NAT; i += 256)
        Xs[i] = (i < limit) ? X[base + i] : 0.f;
    __syncthreads();

    int rg = tid >> 5;
    int cg = tid & 31;

    ull acc[8][2];
    {
        const ull* Bu = (const ull*)B;
        ull b0 = Bu[cg * 2], b1 = Bu[cg * 2 + 1];
#pragma unroll
        for (int i = 0; i < 8; i++) { acc[i][0] = b0; acc[i][1] = b1; }
    }
    const ulonglong2* Wu = (const ulonglong2*)W;
#pragma unroll 4
    for (int k = 0; k < NAT; k++) {
        ulonglong2 bv = Wu[k * 32 + cg];
#pragma unroll
        for (int i = 0; i < 8; i++) {
            ull ad = dup2(Xs[(rg * 8 + i) * NAT + k]);
            acc[i][0] = ffma2(ad, bv.x, acc[i][0]);
            acc[i][1] = ffma2(ad, bv.y, acc[i][1]);
        }
    }
#pragma unroll
    for (int i = 0; i < 8; i++) {
        int r = row0 + rg * 8 + i;
        if (r < N) {
            float2 p0 = unpk(acc[i][0]), p1 = unpk(acc[i][1]);
            float4 o; o.x = p0.x; o.y = p0.y; o.z = p1.x; o.w = p1.y;
            ((float4*)H)[r * 32 + cg] = o;
        }
    }
}

// ---------------- CSR build: hist / scan / fill ----------------
__global__ __launch_bounds__(256) void hist_kernel(
    const int* __restrict__ EI, int* __restrict__ deg, int E)
{
    int e = blockIdx.x * blockDim.x + threadIdx.x;
    if (e < E) atomicAdd(&deg[EI[E + e]], 1);
}

__global__ __launch_bounds__(1024) void scan_block(
    const int* __restrict__ deg, int* __restrict__ off,
    int* __restrict__ bsum, int N)
{
    __shared__ int s[1024];
    int tid = threadIdx.x;
    int i = blockIdx.x * 1024 + tid;
    int v = (i < N) ? deg[i] : 0;
    s[tid] = v;
    __syncthreads();
#pragma unroll
    for (int d = 1; d < 1024; d <<= 1) {
        int t = (tid >= d) ? s[tid - d] : 0;
        __syncthreads();
        s[tid] += t;
        __syncthreads();
    }
    if (i < N) off[i] = s[tid] - v;      // exclusive
    if (tid == 1023) bsum[blockIdx.x] = s[1023];
}

__global__ __launch_bounds__(64) void scan_partials(int* __restrict__ bsum, int nb)
{
    __shared__ int s[64];
    int tid = threadIdx.x;
    int v = (tid < nb) ? bsum[tid] : 0;
    s[tid] = v;
    __syncthreads();
#pragma unroll
    for (int d = 1; d < 64; d <<= 1) {
        int t = (tid >= d) ? s[tid - d] : 0;
        __syncthreads();
        s[tid] += t;
        __syncthreads();
    }
    if (tid < nb) bsum[tid] = s[tid] - v;  // exclusive
}

__global__ __launch_bounds__(1024) void scan_add(
    int* __restrict__ off, const int* __restrict__ bsum, int N, int E)
{
    int i = blockIdx.x * 1024 + threadIdx.x;
    if (i < N) off[i] += bsum[blockIdx.x];
    if (i == 0) off[N] = E;
}

__global__ __launch_bounds__(256) void fill_kernel(
    const int* __restrict__ EI, const int* __restrict__ off,
    int* __restrict__ cur, int* __restrict__ csr, int E)
{
    int e = blockIdx.x * blockDim.x + threadIdx.x;
    if (e >= E) return;
    int dst = EI[E + e];
    int pos = atomicAdd(&cur[dst], 1);
    csr[off[dst] + pos] = EI[e];
}

// ---------------- gather: M[r] = H[r] + sum_{s in nbr(r)} H[s] ----------------
__global__ __launch_bounds__(256) void gather_kernel(
    const float* __restrict__ H, float* __restrict__ M,
    const int* __restrict__ off, const int* __restrict__ csr, int N)
{
    int gid = blockIdx.x * blockDim.x + threadIdx.x;
    int r = gid >> 5;
    if (r >= N) return;
    int lane = gid & 31;
    const float4* H4 = (const float4*)H;
    float4 acc = H4[r * 32 + lane];     // self term (GIN eps=0)
    int j = off[r], end = off[r + 1];
    for (; j + 4 <= end; j += 4) {
        int s0 = csr[j], s1 = csr[j + 1], s2 = csr[j + 2], s3 = csr[j + 3];
        float4 v0 = H4[s0 * 32 + lane];
        float4 v1 = H4[s1 * 32 + lane];
        float4 v2 = H4[s2 * 32 + lane];
        float4 v3 = H4[s3 * 32 + lane];
        acc.x += (v0.x + v1.x) + (v2.x + v3.x);
        acc.y += (v0.y + v1.y) + (v2.y + v3.y);
        acc.z += (v0.z + v1.z) + (v2.z + v3.z);
        acc.w += (v0.w + v1.w) + (v2.w + v3.w);
    }
    for (; j < end; j++) {
        float4 v = H4[csr[j] * 32 + lane];
        acc.x += v.x; acc.y += v.y; acc.z += v.z; acc.w += v.w;
    }
    ((float4*)M)[r * 32 + lane] = acc;
}

// ------- fused layer: Out = relu(M@W1+b1)@W2 + b2 + Res ; BN stats.
// cp.async double-buffered weight staging; T tile lives in registers then
// overwrites Ms+WbufA smem region.
// smem layout (bytes): [0,32768) Ms / later Ts[0:64K); [32768,65536) WbufA;
//                      [65536,98304) WbufB.
__global__ __launch_bounds__(256, 2) void fused_layer(
    const float* __restrict__ M, const float* __restrict__ Res,
    const float* __restrict__ W1, const float* __restrict__ B1,
    const float* __restrict__ W2, const float* __restrict__ B2,
    float* __restrict__ Out, float* __restrict__ stat, int N)
{
    extern __shared__ float sm[];
    uint32_t sbase;
    asm("{ .reg .u64 t; cvta.to.shared.u64 t, %1; cvt.u32.u64 %0, t; }"
        : "=r"(sbase) : "l"(sm));
    int row0 = blockIdx.x * 64;
    int tid = threadIdx.x;
    int rg = tid >> 5;
    int cg = tid & 31;

    // prefetch W1 chunk 0 (16 k-rows x 256 floats = 16KB)
    {
        const char* src = (const char*)W1;
        uint32_t dst = sbase + 32768;
#pragma unroll
        for (int j = 0; j < 4; j++) {
            int idx = tid + j * 256;
            cp16(dst + idx * 16, src + idx * 16);
        }
        CP_COMMIT();
    }

    // load M tile into Ms (32KB @ 0)
    {
        float4* Ms4 = (float4*)sm;
        const float4* M4 = (const float4*)M;
        int limit4 = N * 32 - row0 * 32;
        for (int i = tid; i < 64 * 32; i += 256)
            Ms4[i] = (i < limit4) ? M4[row0 * 32 + i] : make_float4(0.f, 0.f, 0.f, 0.f);
    }

    // ---- stage A: T[64,256] = relu(M@W1 + b1), acc in registers ----
    ull accA[8][4];
    {
        const ull* B1u = (const ull*)B1;
        ull b0 = B1u[2 * cg], b1 = B1u[2 * cg + 1];
        ull b2 = B1u[64 + 2 * cg], b3 = B1u[64 + 2 * cg + 1];
#pragma unroll
        for (int i = 0; i < 8; i++) {
            accA[i][0] = b0; accA[i][1] = b1; accA[i][2] = b2; accA[i][3] = b3;
        }
    }
    const float4* Ms4r = (const float4*)sm;

    for (int c = 0; c < 8; c++) {
        if (c < 7) {   // prefetch next chunk into other half
            const char* src = (const char*)W1 + (c + 1) * 16384;
            uint32_t dst = sbase + 32768 + ((c + 1) & 1) * 16384;
#pragma unroll
            for (int j = 0; j < 4; j++) {
                int idx = tid + j * 256;
                cp16(dst + idx * 16, src + idx * 16);
            }
            CP_COMMIT();
            CP_WAIT1();
        } else {
            CP_WAIT0();
        }
        __syncthreads();
        const ulonglong2* WA = (const ulonglong2*)(sm + 8192 + (c & 1) * 4096);
#pragma unroll
        for (int k4l = 0; k4l < 4; k4l++) {
            int k4 = c * 4 + k4l;
            float4 a4[8];
#pragma unroll
            for (int i = 0; i < 8; i++) a4[i] = Ms4r[(rg * 8 + i) * 32 + k4];
#pragma unroll
            for (int kk = 0; kk < 4; kk++) {
                int kl = k4l * 4 + kk;
                ulonglong2 bv0 = WA[kl * 64 + cg];
                ulonglong2 bv1 = WA[kl * 64 + 32 + cg];
#pragma unroll
                for (int i = 0; i < 8; i++) {
                    float a = (kk == 0) ? a4[i].x : (kk == 1) ? a4[i].y
                            : (kk == 2) ? a4[i].z : a4[i].w;
                    ull ad = dup2(a);
                    accA[i][0] = ffma2(ad, bv0.x, accA[i][0]);
                    accA[i][1] = ffma2(ad, bv0.y, accA[i][1]);
                    accA[i][2] = ffma2(ad, bv1.x, accA[i][2]);
                    accA[i][3] = ffma2(ad, bv1.y, accA[i][3]);
                }
            }
        }
        __syncthreads();
    }

    // prefetch W2 chunk 0 into WbufB (32 k-rows x 128 floats = 16KB)
    {
        const char* src = (const char*)W2;
        uint32_t dst = sbase + 65536;
#pragma unroll
        for (int j = 0; j < 4; j++) {
            int idx = tid + j * 256;
            cp16(dst + idx * 16, src + idx * 16);
        }
        CP_COMMIT();
    }

    // write Ts (relu) to smem [0, 64KB) — overwrites Ms + WbufA
#pragma unroll
    for (int i = 0; i < 8; i++) {
        float2 p0 = unpk(accA[i][0]), p1 = unpk(accA[i][1]);
        float2 p2 = unpk(accA[i][2]), p3 = unpk(accA[i][3]);
        float4 o0, o1;
        o0.x = fmaxf(p0.x, 0.f); o0.y = fmaxf(p0.y, 0.f);
        o0.z = fmaxf(p1.x, 0.f); o0.w = fmaxf(p1.y, 0.f);
        o1.x = fmaxf(p2.x, 0.f); o1.y = fmaxf(p2.y, 0.f);
        o1.z = fmaxf(p3.x, 0.f); o1.w = fmaxf(p3.y, 0.f);
        float* tp = sm + (rg * 8 + i) * 256;
        *(float4*)(tp + 4 * cg) = o0;
        *(float4*)(tp + 128 + 4 * cg) = o1;
    }

    // ---- stage B: Out[64,128] = T@W2 + b2 + Res ----
    ull accB[8][2];
    {
        const ull* B2u = (const ull*)B2;
        ull b0 = B2u[2 * cg], b1 = B2u[2 * cg + 1];
#pragma unroll
        for (int i = 0; i < 8; i++) { accB[i][0] = b0; accB[i][1] = b1; }
    }
    const float4* Ts4 = (const float4*)sm;

    for (int c = 0; c < 8; c++) {
        if (c < 7) {
            const char* src = (const char*)W2 + (c + 1) * 16384;
            uint32_t dst = sbase + 65536 + ((c + 1) & 1) * 16384;
#pragma unroll
            for (int j = 0; j < 4; j++) {
                int idx = tid + j * 256;
                cp16(dst + idx * 16, src + idx * 16);
            }
            CP_COMMIT();
            CP_WAIT1();
        } else {
            CP_WAIT0();
        }
        __syncthreads();
        const ulonglong2* WB = (const ulonglong2*)(sm + 16384 + (c & 1) * 4096);
#pragma unroll
        for (int k4l = 0; k4l < 8; k4l++) {
            int k4 = c * 8 + k4l;
            float4 a4[8];
#pragma unroll
            for (int i = 0; i < 8; i++) a4[i] = Ts4[(rg * 8 + i) * 64 + k4];
#pragma unroll
            for (int kk = 0; kk < 4; kk++) {
                int kl = k4l * 4 + kk;
                ulonglong2 bv = WB[kl * 32 + cg];
#pragma unroll
                for (int i = 0; i < 8; i++) {
                    float a = (kk == 0) ? a4[i].x : (kk == 1) ? a4[i].y
                            : (kk == 2) ? a4[i].z : a4[i].w;
                    ull ad = dup2(a);
                    accB[i][0] = ffma2(ad, bv.x, accB[i][0]);
                    accB[i][1] = ffma2(ad, bv.y, accB[i][1]);
                }
            }
        }
        __syncthreads();
    }

    // ---- epilogue: residual, write, BN stat reduction ----
    float* sred = sm;
    sred[tid] = 0.f;
    __syncthreads();

    float ls0=0,ls1=0,ls2=0,ls3=0, lq0=0,lq1=0,lq2=0,lq3=0;
#pragma unroll
    for (int i = 0; i < 8; i++) {
        int r = row0 + rg * 8 + i;
        if (r < N) {
            float2 p0 = unpk(accB[i][0]), p1 = unpk(accB[i][1]);
            float4 rv = ((const float4*)Res)[r * 32 + cg];
            float4 o;
            o.x = p0.x + rv.x;
            o.y = p0.y + rv.y;
            o.z = p1.x + rv.z;
            o.w = p1.y + rv.w;
            ((float4*)Out)[r * 32 + cg] = o;
            ls0 += o.x; ls1 += o.y; ls2 += o.z; ls3 += o.w;
            lq0 += o.x*o.x; lq1 += o.y*o.y; lq2 += o.z*o.z; lq3 += o.w*o.w;
        }
    }
    int c0 = cg * 4;
    atomicAdd(&sred[c0 + 0], ls0); atomicAdd(&sred[c0 + 1], ls1);
    atomicAdd(&sred[c0 + 2], ls2); atomicAdd(&sred[c0 + 3], ls3);
    atomicAdd(&sred[EMB + c0 + 0], lq0); atomicAdd(&sred[EMB + c0 + 1], lq1);
    atomicAdd(&sred[EMB + c0 + 2], lq2); atomicAdd(&sred[EMB + c0 + 3], lq3);
    __syncthreads();
    atomicAdd(&stat[tid], sred[tid]);
}

// ---------------- batchnorm apply (+optional relu) ----------------
__global__ __launch_bounds__(256) void bn_apply(
    const float* __restrict__ In, float* __restrict__ Out,
    const float* __restrict__ stat, const float* __restrict__ G,
    const float* __restrict__ Be, int N, int doRelu)
{
    __shared__ float sc[EMB], sh[EMB];
    if (threadIdx.x < EMB) {
        int c = threadIdx.x;
        float invN = 1.f / (float)N;
        float mu = stat[c] * invN;
        float var = stat[EMB + c] * invN - mu * mu;
        float s = rsqrtf(var + BN_EPS) * G[c];
        sc[c] = s;
        sh[c] = Be[c] - mu * s;
    }
    __syncthreads();
    int total4 = N * 32;
    for (int i = blockIdx.x * blockDim.x + threadIdx.x; i < total4; i += gridDim.x * blockDim.x) {
        int c4 = (i & 31) * 4;
        float4 v = ((const float4*)In)[i];
        v.x = v.x * sc[c4 + 0] + sh[c4 + 0];
        v.y = v.y * sc[c4 + 1] + sh[c4 + 1];
        v.z = v.z * sc[c4 + 2] + sh[c4 + 2];
        v.w = v.w * sc[c4 + 3] + sh[c4 + 3];
        if (doRelu) {
            v.x = fmaxf(v.x, 0.f); v.y = fmaxf(v.y, 0.f);
            v.z = fmaxf(v.z, 0.f); v.w = fmaxf(v.w, 0.f);
        }
        ((float4*)Out)[i] = v;
    }
}

// ---------------- mean pool (weighted for hydrated) ----------------
__global__ __launch_bounds__(256) void pool_kernel(
    const float* __restrict__ H, const int* __restrict__ batch,
    const int* __restrict__ mask, float* __restrict__ P,
    float* __restrict__ C, int N)
{
    int gid = blockIdx.x * blockDim.x + threadIdx.x;
    int r = gid >> 5;
    if (r >= N) return;
    int lane = gid & 31;
    if (mask && mask[r] == 0) return;
    int g = batch[r];
    float4 v = ((const float4*)H)[r * 32 + lane];
    float* p = P + (size_t)g * EMB + lane * 4;
    asm volatile("red.global.add.v4.f32 [%0], {%1,%2,%3,%4};"
                 :: "l"(p), "f"(v.x), "f"(v.y), "f"(v.z), "f"(v.w) : "memory");
    if (lane == 0) atomicAdd(&C[g], 1.f);
}

// ---------------- head MLP: [NG,256] -> 128 -> 64 -> 1 ----------------
__global__ __launch_bounds__(128) void head_kernel(
    const float* __restrict__ Ps, const float* __restrict__ Cs,
    const float* __restrict__ Ph, const float* __restrict__ Ch,
    const float* __restrict__ fw1, const float* __restrict__ fb1,
    const float* __restrict__ fw2, const float* __restrict__ fb2,
    const float* __restrict__ fw3, const float* __restrict__ fb3,
    float* __restrict__ out)
{
    __shared__ float rep[256], o1[128], o2[64];
    int g = blockIdx.x;
    int tid = threadIdx.x;
    float cs = fmaxf(Cs[g], 1.f), ch = fmaxf(Ch[g], 1.f);
    rep[tid] = Ps[g * EMB + tid] / cs;
    rep[128 + tid] = Ph[g * EMB + tid] / ch;
    __syncthreads();
    float s = fb1[tid];
    for (int k = 0; k < 256; k++) s += rep[k] * fw1[k * 128 + tid];
    o1[tid] = fmaxf(s, 0.f);
    __syncthreads();
    if (tid < 64) {
        float s2 = fb2[tid];
        for (int k = 0; k < 128; k++) s2 += o1[k] * fw2[k * 64 + tid];
        o2[tid] = fmaxf(s2, 0.f);
    }
    __syncthreads();
    if (tid == 0) {
        float s3 = fb3[0];
        for (int k = 0; k < 64; k++) s3 += o2[k] * fw3[k];
        out[g] = s3;
    }
}

// ---------------- launcher ----------------
extern "C" void kernel_launch(void* const* d_in, const int* in_sizes, int n_in,
                              void* d_out, int out_size)
{
    const float* solute_x = (const float*)d_in[0];
    const float* hyd_x    = (const float*)d_in[1];
    const float* Wx_s = (const float*)d_in[2];
    const float* bx_s = (const float*)d_in[3];
    const float* Wx_h = (const float*)d_in[4];
    const float* bx_h = (const float*)d_in[5];
    const float* w1_s = (const float*)d_in[6];
    const float* b1_s = (const float*)d_in[7];
    const float* w2_s = (const float*)d_in[8];
    const float* b2_s = (const float*)d_in[9];
    const float* gg_s = (const float*)d_in[10];
    const float* be_s = (const float*)d_in[11];
    const float* w1_h = (const float*)d_in[12];
    const float* b1_h = (const float*)d_in[13];
    const float* w2_h = (const float*)d_in[14];
    const float* b2_h = (const float*)d_in[15];
    const float* gg_h = (const float*)d_in[16];
    const float* be_h = (const float*)d_in[17];
    const float* fcw1 = (const float*)d_in[18];
    const float* fcb1 = (const float*)d_in[19];
    const float* fcw2 = (const float*)d_in[20];
    const float* fcb2 = (const float*)d_in[21];
    const float* fcw3 = (const float*)d_in[22];
    const float* fcb3 = (const float*)d_in[23];
    const int* ei_s   = (const int*)d_in[24];
    const int* ei_h   = (const int*)d_in[25];
    const int* batch_s = (const int*)d_in[26];
    const int* batch_h = (const int*)d_in[27];
    const int* mask_h  = (const int*)d_in[28];

    float *hs, *ms, *ts, *hh, *mh, *th, *ps, *ph, *cs, *ch, *stat;
    int *deg, *off_s, *off_h, *csr_s, *csr_h, *bsum;
    cudaGetSymbolAddress((void**)&hs, g_hs);
    cudaGetSymbolAddress((void**)&ms, g_ms);
    cudaGetSymbolAddress((void**)&ts, g_ts);
    cudaGetSymbolAddress((void**)&hh, g_hh);
    cudaGetSymbolAddress((void**)&mh, g_mh);
    cudaGetSymbolAddress((void**)&th, g_th);
    cudaGetSymbolAddress((void**)&ps, g_pool_s);
    cudaGetSymbolAddress((void**)&ph, g_pool_h);
    cudaGetSymbolAddress((void**)&cs, g_cnt_s);
    cudaGetSymbolAddress((void**)&ch, g_cnt_h);
    cudaGetSymbolAddress((void**)&stat, g_stat);
    cudaGetSymbolAddress((void**)&deg, g_deg);
    cudaGetSymbolAddress((void**)&off_s, g_off_s);
    cudaGetSymbolAddress((void**)&off_h, g_off_h);
    cudaGetSymbolAddress((void**)&csr_s, g_csr_s);
    cudaGetSymbolAddress((void**)&csr_h, g_csr_h);
    cudaGetSymbolAddress((void**)&bsum, g_bsum);

    cudaFuncSetAttribute(fused_layer, cudaFuncAttributeMaxDynamicSharedMemorySize, 98304);

    const int nbS = (NSOL + 63) / 64;
    const int nbH = (NHYD + 63) / 64;
    const int sbS = (NSOL + 1023) / 1024;   // 40
    const int sbH = (NHYD + 1023) / 1024;   // 59

    // ---- CSR build: solute ----
    cudaMemsetAsync(deg, 0, NSOL * sizeof(int));
    hist_kernel<<<(ESOL + 255) / 256, 256>>>(ei_s, deg, ESOL);
    scan_block<<<sbS, 1024>>>(deg, off_s, bsum, NSOL);
    scan_partials<<<1, 64>>>(bsum, sbS);
    scan_add<<<sbS, 1024>>>(off_s, bsum, NSOL, ESOL);
    cudaMemsetAsync(deg, 0, NSOL * sizeof(int));
    fill_kernel<<<(ESOL + 255) / 256, 256>>>(ei_s, off_s, deg, csr_s, ESOL);
    // ---- CSR build: hydrated ----
    cudaMemsetAsync(deg, 0, NHYD * sizeof(int));
    hist_kernel<<<(EHYD + 255) / 256, 256>>>(ei_h, deg, EHYD);
    scan_block<<<sbH, 1024>>>(deg, off_h, bsum, NHYD);
    scan_partials<<<1, 64>>>(bsum, sbH);
    scan_add<<<sbH, 1024>>>(off_h, bsum, NHYD, EHYD);
    cudaMemsetAsync(deg, 0, NHYD * sizeof(int));
    fill_kernel<<<(EHYD + 255) / 256, 256>>>(ei_h, off_h, deg, csr_h, EHYD);

    // ---- input projections ----
    proj_kernel<<<nbS, 256>>>(solute_x, Wx_s, bx_s, hs, NSOL);
    proj_kernel<<<nbH, 256>>>(hyd_x, Wx_h, bx_h, hh, NHYD);

    for (int l = 0; l < NL; l++) {
        int notLast = (l < NL - 1) ? 1 : 0;
        // ---- solute branch ----
        gather_kernel<<<(NSOL * 32 + 255) / 256, 256>>>(hs, ms, off_s, csr_s, NSOL);
        cudaMemsetAsync(stat, 0, 2 * EMB * sizeof(float));
        fused_layer<<<nbS, 256, 98304>>>(ms, hs,
            w1_s + (size_t)l * EMB * 2 * EMB, b1_s + l * 2 * EMB,
            w2_s + (size_t)l * 2 * EMB * EMB, b2_s + l * EMB,
            ts, stat, NSOL);
        bn_apply<<<1024, 256>>>(ts, hs, stat, gg_s + l * EMB, be_s + l * EMB,
                                NSOL, notLast);
        // ---- hydrated branch ----
        gather_kernel<<<(NHYD * 32 + 255) / 256, 256>>>(hh, mh, off_h, csr_h, NHYD);
        cudaMemsetAsync(stat, 0, 2 * EMB * sizeof(float));
        fused_layer<<<nbH, 256, 98304>>>(mh, hh,
            w1_h + (size_t)l * EMB * 2 * EMB, b1_h + l * 2 * EMB,
            w2_h + (size_t)l * 2 * EMB * EMB, b2_h + l * EMB,
            th, stat, NHYD);
        bn_apply<<<1024, 256>>>(th, hh, stat, gg_h + l * EMB, be_h + l * EMB,
                                NHYD, notLast);
    }

    // pooling
    cudaMemsetAsync(ps, 0, (size_t)NGR * EMB * sizeof(float));
    cudaMemsetAsync(ph, 0, (size_t)NGR * EMB * sizeof(float));
    cudaMemsetAsync(cs, 0, NGR * sizeof(float));
    cudaMemsetAsync(ch, 0, NGR * sizeof(float));
    pool_kernel<<<(NSOL * 32 + 255) / 256, 256>>>(hs, batch_s, nullptr, ps, cs, NSOL);
    pool_kernel<<<(NHYD * 32 + 255) / 256, 256>>>(hh, batch_h, mask_h, ph, ch, NHYD);

    // head MLP
    head_kernel<<<NGR, 128>>>(ps, cs, ph, ch, fcw1, fcb1, fcw2, fcb2, fcw3, fcb3,
                              (float*)d_out);
}